// round 12
// baseline (speedup 1.0000x reference)
#include <cuda_runtime.h>
#include <cuda_fp16.h>
#include <mma.h>
#include <cstdint>

using namespace nvcuda;

typedef unsigned long long u64;

// ---------------- packed f32x2 helpers ----------------
__device__ __forceinline__ u64 pk2(float a, float b) {
    u64 r; asm("mov.b64 %0, {%1,%2};" : "=l"(r) : "f"(a), "f"(b)); return r;
}
__device__ __forceinline__ void upk2(u64 v, float& a, float& b) {
    asm("mov.b64 {%0,%1}, %2;" : "=f"(a), "=f"(b) : "l"(v));
}
__device__ __forceinline__ u64 ffma2(u64 a, u64 b, u64 c) {
    u64 d; asm("fma.rn.f32x2 %0, %1, %2, %3;" : "=l"(d) : "l"(a), "l"(b), "l"(c)); return d;
}
__device__ __forceinline__ u64 fmul2(u64 a, u64 b) {
    u64 d; asm("mul.rn.f32x2 %0, %1, %2;" : "=l"(d) : "l"(a), "l"(b)); return d;
}
__device__ __forceinline__ u64 fadd2(u64 a, u64 b) {
    u64 d; asm("add.rn.f32x2 %0, %1, %2;" : "=l"(d) : "l"(a), "l"(b)); return d;
}
__device__ __forceinline__ float tanh_(float x) {
    float t; asm("tanh.approx.f32 %0, %1;" : "=f"(t) : "f"(x)); return t;
}

#define H    1024
#define DIN  784
#define DOUT 10
#define MAXB 16384
#define NK   49           // 49 * 16 = 784 exactly

__device__ float g_xW1[(size_t)MAXB * H];   // x @ W1 (fp32)

// ==================== fp16 single-MMA GEMM: g_xW1 = x @ W1 (R11 verbatim) ====================
#define TSW  24    // A smem k-stride (fp16 elems)
#define BSTR 144   // B smem n-stride (fp16 elems)

__global__ __launch_bounds__(256, 2) void mma_xw1(const float* __restrict__ x,
                                                  const float* __restrict__ W1) {
    __shared__ __half sA[2][128 * TSW];
    __shared__ __half sB[2][16 * BSTR];

    const int tid  = threadIdx.x;
    const int warp = tid >> 5;
    const int m0 = blockIdx.y * 128;
    const int n0 = blockIdx.x * 128;
    const int wm = (warp >> 2) * 64;
    const int wn = (warp & 3) * 32;

    wmma::fragment<wmma::accumulator, 16, 16, 16, float> acc[4][2];
#pragma unroll
    for (int i = 0; i < 4; ++i)
#pragma unroll
        for (int j = 0; j < 2; ++j) wmma::fill_fragment(acc[i][j], 0.0f);

    const int arow = tid >> 1, ach = (tid & 1) * 8;
    const float* asrc = x + (size_t)(m0 + arow) * DIN + ach;
    const int aidx = arow * TSW + ach;
    const int bkr = tid >> 4, bnc = (tid & 15) * 8;
    const float* bsrc = W1 + (size_t)bkr * H + n0 + bnc;
    const int bidx = bkr * BSTR + bnc;

    float4 a0, a1, b0, b1;
    auto ld = [&](int it) {
        a0 = *(const float4*)(asrc + it * 16);
        a1 = *(const float4*)(asrc + it * 16 + 4);
        b0 = *(const float4*)(bsrc + (size_t)it * 16 * H);
        b1 = *(const float4*)(bsrc + (size_t)it * 16 * H + 4);
    };
    auto st = [&](int s) {
        float va[8] = {a0.x, a0.y, a0.z, a0.w, a1.x, a1.y, a1.z, a1.w};
        float vb[8] = {b0.x, b0.y, b0.z, b0.w, b1.x, b1.y, b1.z, b1.w};
        ushort ha[8], hb[8];
#pragma unroll
        for (int i = 0; i < 8; ++i) {
            ha[i] = __half_as_ushort(__float2half_rn(va[i]));
            hb[i] = __half_as_ushort(__float2half_rn(vb[i]));
        }
        *(ushort4*)&sA[s][aidx]     = make_ushort4(ha[0], ha[1], ha[2], ha[3]);
        *(ushort4*)&sA[s][aidx + 4] = make_ushort4(ha[4], ha[5], ha[6], ha[7]);
        *(ushort4*)&sB[s][bidx]     = make_ushort4(hb[0], hb[1], hb[2], hb[3]);
        *(ushort4*)&sB[s][bidx + 4] = make_ushort4(hb[4], hb[5], hb[6], hb[7]);
    };

    ld(0); st(0);
    ld(1);

    for (int it = 0; it < NK; ++it) {
        __syncthreads();
        if (it + 1 < NK) st((it + 1) & 1);
        if (it + 2 < NK) ld(it + 2);

        const int s = it & 1;
        wmma::fragment<wmma::matrix_b, 16, 16, 16, __half, wmma::row_major> bf[2];
#pragma unroll
        for (int j = 0; j < 2; ++j)
            wmma::load_matrix_sync(bf[j], &sB[s][wn + j * 16], BSTR);
#pragma unroll
        for (int i = 0; i < 4; ++i) {
            wmma::fragment<wmma::matrix_a, 16, 16, 16, __half, wmma::row_major> af;
            wmma::load_matrix_sync(af, &sA[s][(wm + i * 16) * TSW], TSW);
#pragma unroll
            for (int j = 0; j < 2; ++j)
                wmma::mma_sync(acc[i][j], af, bf[j], acc[i][j]);
        }
    }

#pragma unroll
    for (int i = 0; i < 4; ++i)
#pragma unroll
        for (int j = 0; j < 2; ++j) {
            float* C = g_xW1 + (size_t)(m0 + wm + i * 16) * H + (n0 + wn + j * 16);
            wmma::store_matrix_sync(C, acc[i][j], H, wmma::mem_row_major);
        }
}

// ==================== Kernel 2: 50-step settle, GROUP-PIPELINED ====================
// Rows split into G0={0,1}, G1={2,3} (independent). Half-step pipeline:
//   A(G0) | bar | B(G0)+A(G1) | bar | B(G1)+A(G0,next) | bar | ...
// Phase-B tail hidden under the other group's phase A. Same barrier count,
// same per-element math as R5. wpart/r2 rows disjoint per group (no dbl-buffer).
// B threads: G0 -> tid [0,80), G1 -> tid [128,208); nibble-masked shfls.

// Phase A for one row (r must be a literal for register-array indexing).
#define DO_ROW(rr) do {                                                        \
    ulonglong2 ra = *(const ulonglong2*)&r2_s[(rr)][0];                        \
    ulonglong2 rb = *(const ulonglong2*)&r2_s[(rr)][4];                        \
    u64 rc = *(const u64*)&r2_s[(rr)][8];                                      \
    u64 r2p0 = ra.x, r2p1 = ra.y, r2p2 = rb.x, r2p3 = rb.y, r2p4 = rc;         \
    u64 qacc[5] = {0ULL, 0ULL, 0ULL, 0ULL, 0ULL};                              \
    _Pragma("unroll")                                                          \
    for (int j = 0; j < 4; ++j) {                                              \
        float v  = u1v[(rr)][j];                                               \
        float th = tanh_(v);                                                   \
        u64 p2 = fmul2(w2p[j][0], r2p0);                                       \
        p2 = ffma2(w2p[j][1], r2p1, p2);                                       \
        p2 = ffma2(w2p[j][2], r2p2, p2);                                       \
        p2 = ffma2(w2p[j][3], r2p3, p2);                                       \
        p2 = ffma2(w2p[j][4], r2p4, p2);                                       \
        float pa, pb2; upk2(p2, pa, pb2);                                      \
        u64 th2 = pk2(th, th);                                                 \
        _Pragma("unroll")                                                      \
        for (int k = 0; k < 5; ++k) qacc[k] = ffma2(th2, w2p[j][k], qacc[k]);  \
        float t   = (pa + pb2) + c1_s[(rr) * H + tid + 256 * j];               \
        float omt = fmaf(-th, th, 1.0f);                                       \
        u1v[(rr)][j] = fmaf(omt, t, 0.5f * v);                                 \
    }                                                                          \
    _Pragma("unroll")                                                          \
    for (int k = 0; k < 5; ++k)                                                \
        qacc[k] = fadd2(qacc[k], __shfl_xor_sync(0xffffffffu, qacc[k], 16));   \
    if (lane < 16) {                                                           \
        int pIdx = wid * 16 + lane;                                            \
        int chunk = pIdx >> 5, pos = pIdx & 31;                                \
        _Pragma("unroll")                                                      \
        for (int k = 0; k < 5; ++k)                                            \
            wpart[(((rr) * 5 + k) * 4 + chunk) * 33 + pos] = qacc[k];          \
    }                                                                          \
} while (0)

#define DOA(g) do { DO_ROW(2 * (g)); DO_ROW(2 * (g) + 1); } while (0)

__global__ __launch_bounds__(256, 2) void settle_kernel(
    const float* __restrict__ u1g, const float* __restrict__ u2g,
    const float* __restrict__ W2g, const float* __restrict__ b1g,
    const float* __restrict__ b2g, const int* __restrict__ steps_p,
    float* __restrict__ outg)
{
    __shared__ float c1_s[4 * H];
    __shared__ __align__(16) float r2_s[4][12];
    __shared__ u64 wpart[80 * 33];

    const int tid  = threadIdx.x;
    const int lane = tid & 31;
    const int wid  = tid >> 5;
    const int b0   = blockIdx.x * 4;
    const int nsteps = *steps_p;

    u64 w2p[4][5];
#pragma unroll
    for (int j = 0; j < 4; ++j) {
        const float* w = W2g + (tid + 256 * j) * DOUT;
#pragma unroll
        for (int k = 0; k < 5; ++k)
            w2p[j][k] = pk2(w[2 * k] * 0.0625f, w[2 * k + 1] * 0.0625f);
    }

    float u1v[4][4];
#pragma unroll
    for (int r = 0; r < 4; ++r)
#pragma unroll
        for (int j = 0; j < 4; ++j)
            u1v[r][j] = 0.5f * u1g[(size_t)(b0 + r) * H + tid + 256 * j];

    {
        const float4* xs = (const float4*)(g_xW1 + (size_t)b0 * H);
        const float4* bs = (const float4*)b1g;
        float4* dst = (float4*)c1_s;
#pragma unroll
        for (int i = 0; i < 4; ++i) {
            int e = tid + 256 * i;
            float4 xv = xs[e];
            float4 bv = bs[e & 255];
            dst[e] = make_float4(fmaf(0.03125f, xv.x, 0.0625f * bv.x),
                                 fmaf(0.03125f, xv.y, 0.0625f * bv.y),
                                 fmaf(0.03125f, xv.z, 0.0625f * bv.z),
                                 fmaf(0.03125f, xv.w, 0.0625f * bv.w));
        }
    }

    // ---- phase-B thread mapping: two disjoint 80-thread ranges ----
    const bool isB  = (tid < 80) || (tid >= 128 && tid < 208);
    const int  grp  = (tid >= 128) ? 1 : 0;
    const int  local = tid - (grp ? 128 : 0);          // 0..79 when isB
    const int  r_loc = local / 40;
    const int  r_b  = 2 * grp + r_loc;
    const int  rem  = local - 40 * r_loc;
    const int  o_b  = rem >> 2;
    const int  q4   = rem & 3;
    const int  k_b  = o_b >> 1;
    const int  half = o_b & 1;
    const unsigned m4 = 0xFu << (lane & 28);            // nibble shfl mask
    const float* fb = (const float*)(wpart + ((size_t)((r_b * 5 + k_b) * 4 + q4)) * 33);
    const float* fb_pre = (const float*)(wpart + ((size_t)(k_b * 4 + q4)) * 33);

    // ---- pre-pass: colsum(W2)/16 via reduction path (r=0 slots) ----
    {
        u64 qa[5];
#pragma unroll
        for (int k = 0; k < 5; ++k)
            qa[k] = fadd2(fadd2(w2p[0][k], w2p[1][k]), fadd2(w2p[2][k], w2p[3][k]));
#pragma unroll
        for (int k = 0; k < 5; ++k)
            qa[k] = fadd2(qa[k], __shfl_xor_sync(0xffffffffu, qa[k], 16));
        if (lane < 16) {
            int pIdx = wid * 16 + lane;
            int chunk = pIdx >> 5, pos = pIdx & 31;
#pragma unroll
            for (int k = 0; k < 5; ++k)
                wpart[(k * 4 + chunk) * 33 + pos] = qa[k];
        }
    }
    __syncthreads();

    float C2v = 0.0f, wv = 0.0f, r2v = 0.0f;
    if (isB) {
        float s0a = 0, s0b = 0, s1a = 0, s1b = 0;
#pragma unroll
        for (int i = 0; i < 16; ++i) {
            float2 za = *(const float2*)(fb_pre + 4 * i);
            float2 zb = *(const float2*)(fb_pre + 4 * i + 2);
            s0a += za.x; s1a += za.y; s0b += zb.x; s1b += zb.y;
        }
        float s = half ? (s1a + s1b) : (s0a + s0b);
        s += __shfl_xor_sync(m4, s, 1);
        s += __shfl_xor_sync(m4, s, 2);
        C2v = fmaf(8.0f, s, b2g[o_b]);
        wv  = 0.5f * u2g[(b0 + r_b) * DOUT + o_b];
        float tau = tanh_(wv);
        r2v = fmaf(0.5f, tau, 0.5f);
        if (q4 == 0) r2_s[r_b][o_b] = r2v;
    }
    __syncthreads();

    // ---- phase B for this thread's (r_b, o_b) ----
    auto doB = [&]() {
        float s0a = 0, s0b = 0, s1a = 0, s1b = 0;
#pragma unroll
        for (int i = 0; i < 16; ++i) {
            float2 za = *(const float2*)(fb + 4 * i);
            float2 zb = *(const float2*)(fb + 4 * i + 2);
            s0a += za.x; s1a += za.y; s0b += zb.x; s1b += zb.y;
        }
        float sv = half ? (s1a + s1b) : (s0a + s0b);
        sv += __shfl_xor_sync(m4, sv, 1);
        sv += __shfl_xor_sync(m4, sv, 2);
        float gq  = fmaf(8.0f, sv, C2v);
        float tau = tanh_(wv);
        float om  = fmaf(-tau, tau, 1.0f);
        wv = fmaf(0.0625f * om, gq, 0.5f * wv);
        r2v = fmaf(0.5f, tanh_(wv), 0.5f);
        if (q4 == 0) r2_s[r_b][o_b] = r2v;
    };

    // ---- pipelined half-step loop ----
    DOA(0);                         // A(G0, step 0)
    __syncthreads();

    const int nhs = 2 * nsteps - 1;
    for (int hs = 0; hs < nhs; ++hs) {
        if ((hs & 1) == 0) {
            if (isB && grp == 0) doB();   // B(G0)
            DOA(1);                       // A(G1)
        } else {
            if (isB && grp == 1) doB();   // B(G1)
            DOA(0);                       // A(G0, next step)
        }
        __syncthreads();
    }
    if (isB && grp == 1) doB();           // final B(G1)

    if (isB && q4 == 0)
        outg[(b0 + r_b) * DOUT + o_b] = r2v;   // y = sigmoid(u2_final)
}

// ==================== launch ====================
extern "C" void kernel_launch(void* const* d_in, const int* in_sizes, int n_in,
                              void* d_out, int out_size) {
    const float* x     = (const float*)d_in[0];
    const float* u1    = (const float*)d_in[1];
    const float* u2    = (const float*)d_in[2];
    const float* W1    = (const float*)d_in[3];
    const float* W2    = (const float*)d_in[4];
    const float* b1    = (const float*)d_in[5];
    const float* b2    = (const float*)d_in[6];
    const int*   steps = (const int*)d_in[7];
    float* out = (float*)d_out;

    const int B = in_sizes[1] / H;

    mma_xw1<<<dim3(H / 128, B / 128), 256>>>(x, W1);
    settle_kernel<<<B / 4, 256>>>(u1, u2, W2, b1, b2, steps, out);
}

// round 13
// speedup vs baseline: 1.0835x; 1.0835x over previous
#include <cuda_runtime.h>
#include <cuda_fp16.h>
#include <mma.h>
#include <cstdint>

using namespace nvcuda;

typedef unsigned long long u64;

// ---------------- packed f32x2 helpers ----------------
__device__ __forceinline__ u64 pk2(float a, float b) {
    u64 r; asm("mov.b64 %0, {%1,%2};" : "=l"(r) : "f"(a), "f"(b)); return r;
}
__device__ __forceinline__ void upk2(u64 v, float& a, float& b) {
    asm("mov.b64 {%0,%1}, %2;" : "=f"(a), "=f"(b) : "l"(v));
}
__device__ __forceinline__ u64 ffma2(u64 a, u64 b, u64 c) {
    u64 d; asm("fma.rn.f32x2 %0, %1, %2, %3;" : "=l"(d) : "l"(a), "l"(b), "l"(c)); return d;
}
__device__ __forceinline__ u64 fmul2(u64 a, u64 b) {
    u64 d; asm("mul.rn.f32x2 %0, %1, %2;" : "=l"(d) : "l"(a), "l"(b)); return d;
}
__device__ __forceinline__ u64 fadd2(u64 a, u64 b) {
    u64 d; asm("add.rn.f32x2 %0, %1, %2;" : "=l"(d) : "l"(a), "l"(b)); return d;
}
__device__ __forceinline__ float tanh_(float x) {
    float t; asm("tanh.approx.f32 %0, %1;" : "=f"(t) : "f"(x)); return t;
}

#define H     1024
#define DIN   784
#define DOUT  10
#define MAXB  16384
#define KPAD2 800          // 25 * 32; zero-init padding beyond 784
#define NI    25           // GEMM outer iterations (K-step 32)

__device__ float g_xW1[(size_t)MAXB * H];                        // x @ W1 (fp32)
__device__ __align__(16) __half g_xh[(size_t)MAXB * KPAD2];      // x  fp16 [m][k], zero-pad
__device__ __align__(16) __half g_w1h[(size_t)KPAD2 * H];        // W1 fp16 [k][n], zero-pad

// ==================== conv kernels: fp32 -> fp16 (one-time) ====================
__global__ __launch_bounds__(256) void conv_x(const float* __restrict__ x, int B) {
    int u = blockIdx.x * 256 + threadIdx.x;            // (m, 8-elem unit)
    if (u >= B * (KPAD2 / 8)) return;
    int m = u / (KPAD2 / 8), ku = u - m * (KPAD2 / 8);
    int k = ku * 8;
    ushort h[8];
#pragma unroll
    for (int i = 0; i < 8; ++i)
        h[i] = (k + i < DIN)
             ? __half_as_ushort(__float2half_rn(x[(size_t)m * DIN + k + i]))
             : (ushort)0;
    *(ushort4*)(g_xh + (size_t)m * KPAD2 + k)     = make_ushort4(h[0], h[1], h[2], h[3]);
    *(ushort4*)(g_xh + (size_t)m * KPAD2 + k + 4) = make_ushort4(h[4], h[5], h[6], h[7]);
}

__global__ __launch_bounds__(256) void conv_w(const float* __restrict__ W1) {
    int u = blockIdx.x * 256 + threadIdx.x;            // (k, 8-elem n unit)
    if (u >= KPAD2 * (H / 8)) return;
    int k = u / (H / 8), n = (u - k * (H / 8)) * 8;
    ushort h[8];
#pragma unroll
    for (int i = 0; i < 8; ++i)
        h[i] = (k < DIN)
             ? __half_as_ushort(__float2half_rn(W1[(size_t)k * H + n + i]))
             : (ushort)0;
    *(ushort4*)(g_w1h + (size_t)k * H + n)     = make_ushort4(h[0], h[1], h[2], h[3]);
    *(ushort4*)(g_w1h + (size_t)k * H + n + 4) = make_ushort4(h[4], h[5], h[6], h[7]);
}

// ==================== fp16 MMA GEMM, K-step 32, cp.async, 2-stage ====================
// CTA tile 128x128. A stride 40 elems (80B rows, conflict-free), B stride 136
// (272B rows, conflict-free). 25 iters, 1 barrier each, cp.async overlapped.
#define ASTR 40
#define BSTR2 136

__device__ __forceinline__ void cp16(uint32_t dst, const void* src) {
    asm volatile("cp.async.cg.shared.global [%0], [%1], 16;" :: "r"(dst), "l"(src));
}

__global__ __launch_bounds__(256, 2) void mma_xw1() {
    __shared__ __half sA[2][128 * ASTR];    // 20.5 KB
    __shared__ __half sB[2][32 * BSTR2];    // 17.4 KB

    const int tid  = threadIdx.x;
    const int warp = tid >> 5;
    const int m0 = blockIdx.y * 128;
    const int n0 = blockIdx.x * 128;
    const int wm = (warp >> 2) * 64;
    const int wn = (warp & 3) * 32;

    wmma::fragment<wmma::accumulator, 16, 16, 16, float> acc[4][2];
#pragma unroll
    for (int i = 0; i < 4; ++i)
#pragma unroll
        for (int j = 0; j < 2; ++j) wmma::fill_fragment(acc[i][j], 0.0f);

    // A: row = tid>>1, 16 elems at (tid&1)*16 (+0,+8). B: krow = tid>>3, 16 cols at (tid&7)*16.
    const int arow = tid >> 1, ak = (tid & 1) * 16;
    const __half* asrc = g_xh + (size_t)(m0 + arow) * KPAD2 + ak;
    const int aoff = arow * ASTR + ak;
    const int bkr = tid >> 3, bnc = (tid & 7) * 16;
    const __half* bsrc = g_w1h + (size_t)bkr * H + n0 + bnc;
    const int boff = bkr * BSTR2 + bnc;

    auto cpAB = [&](int it, int s) {
        cp16((uint32_t)__cvta_generic_to_shared(&sA[s][aoff]),     asrc + it * 32);
        cp16((uint32_t)__cvta_generic_to_shared(&sA[s][aoff + 8]), asrc + it * 32 + 8);
        cp16((uint32_t)__cvta_generic_to_shared(&sB[s][boff]),     bsrc + (size_t)it * 32 * H);
        cp16((uint32_t)__cvta_generic_to_shared(&sB[s][boff + 8]), bsrc + (size_t)it * 32 * H + 8);
        asm volatile("cp.async.commit_group;" ::: "memory");
    };

    cpAB(0, 0);

    for (int it = 0; it < NI; ++it) {
        asm volatile("cp.async.wait_group 0;" ::: "memory");
        __syncthreads();                       // stage[it&1] full; other stage free
        if (it + 1 < NI) cpAB(it + 1, (it + 1) & 1);

        const int s = it & 1;
#pragma unroll
        for (int ks = 0; ks < 32; ks += 16) {
            wmma::fragment<wmma::matrix_b, 16, 16, 16, __half, wmma::row_major> bf[2];
#pragma unroll
            for (int j = 0; j < 2; ++j)
                wmma::load_matrix_sync(bf[j], &sB[s][ks * BSTR2 + wn + j * 16], BSTR2);
#pragma unroll
            for (int i = 0; i < 4; ++i) {
                wmma::fragment<wmma::matrix_a, 16, 16, 16, __half, wmma::row_major> af;
                wmma::load_matrix_sync(af, &sA[s][(wm + i * 16) * ASTR + ks], ASTR);
#pragma unroll
                for (int j = 0; j < 2; ++j)
                    wmma::mma_sync(acc[i][j], af, bf[j], acc[i][j]);
            }
        }
    }

#pragma unroll
    for (int i = 0; i < 4; ++i)
#pragma unroll
        for (int j = 0; j < 2; ++j) {
            float* C = g_xW1 + (size_t)(m0 + wm + i * 16) * H + (n0 + wn + j * 16);
            wmma::store_matrix_sync(C, acc[i][j], H, wmma::mem_row_major);
        }
}

// ==================== Kernel 2: 50-step settle (R5 verbatim — frozen) ====================
__global__ __launch_bounds__(256, 2) void settle_kernel(
    const float* __restrict__ u1g, const float* __restrict__ u2g,
    const float* __restrict__ W2g, const float* __restrict__ b1g,
    const float* __restrict__ b2g, const int* __restrict__ steps_p,
    float* __restrict__ outg)
{
    __shared__ float c1_s[4 * H];
    __shared__ __align__(16) float r2_s[4][12];
    __shared__ u64 wpart[80 * 33];

    const int tid  = threadIdx.x;
    const int lane = tid & 31;
    const int wid  = tid >> 5;
    const int b0   = blockIdx.x * 4;
    const int nsteps = *steps_p;

    u64 w2p[4][5];
#pragma unroll
    for (int j = 0; j < 4; ++j) {
        const float* w = W2g + (tid + 256 * j) * DOUT;
#pragma unroll
        for (int k = 0; k < 5; ++k)
            w2p[j][k] = pk2(w[2 * k] * 0.0625f, w[2 * k + 1] * 0.0625f);
    }

    float u1v[4][4];
#pragma unroll
    for (int r = 0; r < 4; ++r)
#pragma unroll
        for (int j = 0; j < 4; ++j)
            u1v[r][j] = 0.5f * u1g[(size_t)(b0 + r) * H + tid + 256 * j];

    {
        const float4* xs = (const float4*)(g_xW1 + (size_t)b0 * H);
        const float4* bs = (const float4*)b1g;
        float4* dst = (float4*)c1_s;
#pragma unroll
        for (int i = 0; i < 4; ++i) {
            int e = tid + 256 * i;
            float4 xv = xs[e];
            float4 bv = bs[e & 255];
            dst[e] = make_float4(fmaf(0.03125f, xv.x, 0.0625f * bv.x),
                                 fmaf(0.03125f, xv.y, 0.0625f * bv.y),
                                 fmaf(0.03125f, xv.z, 0.0625f * bv.z),
                                 fmaf(0.03125f, xv.w, 0.0625f * bv.w));
        }
    }

    const bool pb = tid < 160;
    const int r_b  = tid / 40;
    const int rem  = tid - 40 * r_b;
    const int o_b  = rem >> 2;
    const int q4   = rem & 3;
    const int k_b  = o_b >> 1;
    const int half = o_b & 1;
    const float* fb = (const float*)(wpart + ((size_t)((r_b * 5 + k_b) * 4 + q4)) * 33);
    const float* fb_pre = (const float*)(wpart + ((size_t)(k_b * 4 + q4)) * 33);

    {
        u64 qa[5];
#pragma unroll
        for (int k = 0; k < 5; ++k)
            qa[k] = fadd2(fadd2(w2p[0][k], w2p[1][k]), fadd2(w2p[2][k], w2p[3][k]));
#pragma unroll
        for (int k = 0; k < 5; ++k)
            qa[k] = fadd2(qa[k], __shfl_xor_sync(0xffffffffu, qa[k], 16));
        if (lane < 16) {
            int pIdx = wid * 16 + lane;
            int chunk = pIdx >> 5, pos = pIdx & 31;
#pragma unroll
            for (int k = 0; k < 5; ++k)
                wpart[(k * 4 + chunk) * 33 + pos] = qa[k];
        }
    }
    __syncthreads();

    float C2v = 0.0f, wv = 0.0f, r2v = 0.0f;
    if (pb) {
        float s0a = 0, s0b = 0, s1a = 0, s1b = 0;
#pragma unroll
        for (int i = 0; i < 16; ++i) {
            float2 za = *(const float2*)(fb_pre + 4 * i);
            float2 zb = *(const float2*)(fb_pre + 4 * i + 2);
            s0a += za.x; s1a += za.y; s0b += zb.x; s1b += zb.y;
        }
        float s = half ? (s1a + s1b) : (s0a + s0b);
        s += __shfl_xor_sync(0xffffffffu, s, 1);
        s += __shfl_xor_sync(0xffffffffu, s, 2);
        C2v = fmaf(8.0f, s, b2g[o_b]);
        wv  = 0.5f * u2g[(b0 + r_b) * DOUT + o_b];
        float tau = tanh_(wv);
        r2v = fmaf(0.5f, tau, 0.5f);
        if (q4 == 0) r2_s[r_b][o_b] = r2v;
    }
    __syncthreads();

    for (int s = 0; s < nsteps; ++s) {
#pragma unroll
        for (int r = 0; r < 4; ++r) {
            ulonglong2 ra = *(const ulonglong2*)&r2_s[r][0];
            ulonglong2 rb = *(const ulonglong2*)&r2_s[r][4];
            u64 rc = *(const u64*)&r2_s[r][8];
            u64 r2p[5] = {ra.x, ra.y, rb.x, rb.y, rc};
            u64 qacc[5] = {0ULL, 0ULL, 0ULL, 0ULL, 0ULL};
#pragma unroll
            for (int j = 0; j < 4; ++j) {
                float v  = u1v[r][j];
                float th = tanh_(v);
                u64 p2 = fmul2(w2p[j][0], r2p[0]);
                p2 = ffma2(w2p[j][1], r2p[1], p2);
                p2 = ffma2(w2p[j][2], r2p[2], p2);
                p2 = ffma2(w2p[j][3], r2p[3], p2);
                p2 = ffma2(w2p[j][4], r2p[4], p2);
                float pa, pb2; upk2(p2, pa, pb2);
                u64 th2 = pk2(th, th);
#pragma unroll
                for (int k = 0; k < 5; ++k) qacc[k] = ffma2(th2, w2p[j][k], qacc[k]);
                float t   = (pa + pb2) + c1_s[r * H + tid + 256 * j];
                float omt = fmaf(-th, th, 1.0f);
                u1v[r][j] = fmaf(omt, t, 0.5f * v);
            }
#pragma unroll
            for (int k = 0; k < 5; ++k)
                qacc[k] = fadd2(qacc[k], __shfl_xor_sync(0xffffffffu, qacc[k], 16));
            if (lane < 16) {
                int pIdx = wid * 16 + lane;
                int chunk = pIdx >> 5, pos = pIdx & 31;
#pragma unroll
                for (int k = 0; k < 5; ++k)
                    wpart[((r * 5 + k) * 4 + chunk) * 33 + pos] = qacc[k];
            }
        }
        __syncthreads();

        if (pb) {
            float s0a = 0, s0b = 0, s1a = 0, s1b = 0;
#pragma unroll
            for (int i = 0; i < 16; ++i) {
                float2 za = *(const float2*)(fb + 4 * i);
                float2 zb = *(const float2*)(fb + 4 * i + 2);
                s0a += za.x; s1a += za.y; s0b += zb.x; s1b += zb.y;
            }
            float sv = half ? (s1a + s1b) : (s0a + s0b);
            sv += __shfl_xor_sync(0xffffffffu, sv, 1);
            sv += __shfl_xor_sync(0xffffffffu, sv, 2);
            float gq  = fmaf(8.0f, sv, C2v);
            float tau = tanh_(wv);
            float om  = fmaf(-tau, tau, 1.0f);
            wv = fmaf(0.0625f * om, gq, 0.5f * wv);
            r2v = fmaf(0.5f, tanh_(wv), 0.5f);
            if (q4 == 0) r2_s[r_b][o_b] = r2v;
        }
        __syncthreads();
    }

    if (pb && q4 == 0)
        outg[(b0 + r_b) * DOUT + o_b] = r2v;
}

// ==================== launch ====================
extern "C" void kernel_launch(void* const* d_in, const int* in_sizes, int n_in,
                              void* d_out, int out_size) {
    const float* x     = (const float*)d_in[0];
    const float* u1    = (const float*)d_in[1];
    const float* u2    = (const float*)d_in[2];
    const float* W1    = (const float*)d_in[3];
    const float* W2    = (const float*)d_in[4];
    const float* b1    = (const float*)d_in[5];
    const float* b2    = (const float*)d_in[6];
    const int*   steps = (const int*)d_in[7];
    float* out = (float*)d_out;

    const int B = in_sizes[1] / H;

    conv_x<<<(B * (KPAD2 / 8) + 255) / 256, 256>>>(x, B);
    conv_w<<<(KPAD2 * (H / 8) + 255) / 256, 256>>>(W1);
    mma_xw1<<<dim3(H / 128, B / 128), 256>>>();
    settle_kernel<<<B / 4, 256>>>(u1, u2, W2, b1, b2, steps, out);
}